// round 13
// baseline (speedup 1.0000x reference)
#include <cuda_runtime.h>
#include <cuda_fp16.h>
#include <cstdint>

#define Bb 64
#define Tt 1024
#define Vv 512
#define Ee 256
#define Uu 512
#define ZN 2048  // 4*U
#define NCTA 128
#define NGRP 4          // batch groups
#define GCTA 32         // CTAs per group
#define GB 16           // batches per group

// ---------------- scratch (device globals; no runtime allocation) ----------
__device__ float g_A[(size_t)Tt * Bb * ZN];   // input-side preact [t][b][4U]
__device__ float g_H[(size_t)Tt * Bb * Uu];   // layer stream fp32 [t][b][u]
__device__ __half g_hbuf[2 * 2 * Bb * Uu];    // h split: [buf][plane hi/lo][b][u]
__device__ unsigned g_flag[NCTA * 32];        // per-CTA progress flags, 128B apart

// ---------------- helpers ---------------------------------------------------
__device__ __forceinline__ unsigned ld_acq(const unsigned* p) {
    unsigned v;
    asm volatile("ld.acquire.gpu.global.u32 %0, [%1];" : "=r"(v) : "l"(p) : "memory");
    return v;
}
__device__ __forceinline__ void st_rel(unsigned* p, unsigned v) {
    asm volatile("st.release.gpu.global.u32 [%0], %1;" ::"l"(p), "r"(v) : "memory");
}
__device__ __forceinline__ void cp_async16(unsigned s, const void* g) {
    asm volatile("cp.async.cg.shared.global [%0], [%1], 16;" ::"r"(s), "l"(g)
                 : "memory");
}
__device__ __forceinline__ float fast_tanh(float x) {
    float y;
    asm("tanh.approx.f32 %0, %1;" : "=f"(y) : "f"(x));
    return y;
}
__device__ __forceinline__ float fast_sig(float x) {
    return __fdividef(1.f, 1.f + __expf(-x));
}
__device__ __forceinline__ void mma16816(float& d0, float& d1, float& d2, float& d3,
                                         uint32_t a0, uint32_t a1, uint32_t a2,
                                         uint32_t a3, uint32_t b0, uint32_t b1) {
    asm volatile(
        "mma.sync.aligned.m16n8k16.row.col.f32.f16.f16.f32 "
        "{%0,%1,%2,%3}, {%4,%5,%6,%7}, {%8,%9}, {%0,%1,%2,%3};"
        : "+f"(d0), "+f"(d1), "+f"(d2), "+f"(d3)
        : "r"(a0), "r"(a1), "r"(a2), "r"(a3), "r"(b0), "r"(b1));
}

// ---------------- split-fp16 HMMA GEMM: C = A @ B + bias -------------------
// (verbatim R9/R12 — verified at rel_err 1.6e-5)
template <int AMODE, int OMODE>
__global__ __launch_bounds__(256) void hgemm_kernel(
    const float* __restrict__ Ag, const int* __restrict__ tokens,
    const float* __restrict__ emb, const float* __restrict__ Bg,
    const float* __restrict__ bias, float* __restrict__ C, int K, int Ntot) {
    __shared__ __half AsH[128][40];
    __shared__ __half AsL[128][40];
    __shared__ __half BsH[64][40];
    __shared__ __half BsL[64][40];
    const int tid = threadIdx.x;
    const int m0 = blockIdx.y * 128;
    const int n0 = blockIdx.x * 64;
    const int lane = tid & 31, warp = tid >> 5;
    const int fg = lane >> 2, tg = lane & 3;

    int a_row[4], a_c4[4];
    const float* a_base[4];
#pragma unroll
    for (int i = 0; i < 4; i++) {
        int s = tid + i * 256;
        a_row[i] = s >> 3;
        a_c4[i] = (s & 7) * 4;
        if (AMODE == 1) {
            int gm = m0 + a_row[i];
            int tb = gm & (Bb - 1);
            int tt = gm >> 6;
            int tok = tokens[tb * Tt + tt];
            a_base[i] = emb + (size_t)tok * Ee + a_c4[i];
        } else {
            a_base[i] = Ag + (size_t)(m0 + a_row[i]) * K + a_c4[i];
        }
    }
    int b_kk[2], b_n4[2];
    const float* b_base[2];
#pragma unroll
    for (int i = 0; i < 2; i++) {
        int s = tid + i * 256;
        b_kk[i] = s >> 4;
        b_n4[i] = (s & 15) * 4;
        b_base[i] = Bg + (size_t)b_kk[i] * Ntot + n0 + b_n4[i];
    }

    float acc[8][4];
#pragma unroll
    for (int j = 0; j < 8; j++)
#pragma unroll
        for (int q = 0; q < 4; q++) acc[j][q] = 0.f;

    float4 pa[4], pb[2];
#pragma unroll
    for (int i = 0; i < 4; i++) pa[i] = *(const float4*)a_base[i];
#pragma unroll
    for (int i = 0; i < 2; i++) pb[i] = *(const float4*)b_base[i];

    for (int k0 = 0; k0 < K; k0 += 32) {
#pragma unroll
        for (int i = 0; i < 4; i++) {
            float4 v = pa[i];
            __half2 h01 = __floats2half2_rn(v.x, v.y);
            __half2 h23 = __floats2half2_rn(v.z, v.w);
            float2 f01 = __half22float2(h01);
            float2 f23 = __half22float2(h23);
            __half2 l01 = __floats2half2_rn(v.x - f01.x, v.y - f01.y);
            __half2 l23 = __floats2half2_rn(v.z - f23.x, v.w - f23.y);
            *(__half2*)&AsH[a_row[i]][a_c4[i]] = h01;
            *(__half2*)&AsH[a_row[i]][a_c4[i] + 2] = h23;
            *(__half2*)&AsL[a_row[i]][a_c4[i]] = l01;
            *(__half2*)&AsL[a_row[i]][a_c4[i] + 2] = l23;
        }
#pragma unroll
        for (int i = 0; i < 2; i++) {
            float vv[4] = {pb[i].x, pb[i].y, pb[i].z, pb[i].w};
#pragma unroll
            for (int q = 0; q < 4; q++) {
                int n = b_n4[i] + q;
                __half h = __float2half(vv[q]);
                BsH[n][b_kk[i]] = h;
                BsL[n][b_kk[i]] = __float2half(vv[q] - __half2float(h));
            }
        }
        __syncthreads();

        if (k0 + 32 < K) {
#pragma unroll
            for (int i = 0; i < 4; i++)
                pa[i] = *(const float4*)(a_base[i] + (k0 + 32));
#pragma unroll
            for (int i = 0; i < 2; i++)
                pb[i] = *(const float4*)(b_base[i] + (size_t)(k0 + 32) * Ntot);
        }

#pragma unroll
        for (int k16 = 0; k16 < 2; k16++) {
            const __half* arH = &AsH[warp * 16 + fg][k16 * 16 + 2 * tg];
            uint32_t ah0 = *(const uint32_t*)arH;
            uint32_t ah1 = *(const uint32_t*)(arH + 8 * 40);
            uint32_t ah2 = *(const uint32_t*)(arH + 8);
            uint32_t ah3 = *(const uint32_t*)(arH + 8 * 40 + 8);
            const __half* arL = &AsL[warp * 16 + fg][k16 * 16 + 2 * tg];
            uint32_t al0 = *(const uint32_t*)arL;
            uint32_t al1 = *(const uint32_t*)(arL + 8 * 40);
            uint32_t al2 = *(const uint32_t*)(arL + 8);
            uint32_t al3 = *(const uint32_t*)(arL + 8 * 40 + 8);
#pragma unroll
            for (int j = 0; j < 8; j++) {
                const __half* brH = &BsH[j * 8 + fg][k16 * 16 + 2 * tg];
                uint32_t bh0 = *(const uint32_t*)brH;
                uint32_t bh1 = *(const uint32_t*)(brH + 8);
                const __half* brL = &BsL[j * 8 + fg][k16 * 16 + 2 * tg];
                uint32_t bl0 = *(const uint32_t*)brL;
                uint32_t bl1 = *(const uint32_t*)(brL + 8);
                mma16816(acc[j][0], acc[j][1], acc[j][2], acc[j][3],
                         ah0, ah1, ah2, ah3, bh0, bh1);
                mma16816(acc[j][0], acc[j][1], acc[j][2], acc[j][3],
                         al0, al1, al2, al3, bh0, bh1);
                mma16816(acc[j][0], acc[j][1], acc[j][2], acc[j][3],
                         ah0, ah1, ah2, ah3, bl0, bl1);
            }
        }
        __syncthreads();
    }

    const int rowA = m0 + warp * 16 + fg;
#pragma unroll
    for (int j = 0; j < 8; j++) {
        int col = n0 + j * 8 + 2 * tg;
        float bv0 = bias[col], bv1 = bias[col + 1];
        float r0 = acc[j][0] + bv0, r1 = acc[j][1] + bv1;
        float r2 = acc[j][2] + bv0, r3 = acc[j][3] + bv1;
        if (OMODE == 0) {
            *(float2*)&C[(size_t)rowA * Ntot + col] = make_float2(r0, r1);
            *(float2*)&C[(size_t)(rowA + 8) * Ntot + col] = make_float2(r2, r3);
        } else {
            int t0 = rowA >> 6, b0 = rowA & 63;
            int t1 = (rowA + 8) >> 6, b1 = (rowA + 8) & 63;
            *(float2*)&C[(size_t)b0 * Tt * Vv + (size_t)t0 * Vv + col] =
                make_float2(r0, r1);
            *(float2*)&C[(size_t)b1 * Tt * Vv + (size_t)t1 * Vv + col] =
                make_float2(r2, r3);
        }
    }
}

// ---------------- persistent LSTM layer kernel (flag-mesh sync) ------------
// 4 groups x 32 CTAs, CTA owns 16 units. No group barrier: each CTA publishes
// a monotonic progress flag after writing its h slice; readers acquire-poll
// only the 8 writer flags a k-chunk needs, immediately before issuing that
// chunk's cp.async. Chunk pipeline: issue c0,c1 -> wg1 -> mma c0 -> issue c2
// -> wg1 -> mma c1 -> issue c3 -> wg1 -> mma c2 -> wg0 -> mma c3.
#define HS_ROW_B 1040
#define HS_PLANE (GB * HS_ROW_B)              // 16640
#define WT_OFF (2 * HS_PLANE)                 // 33280
#define WT_ROW_H 520
#define WT_PLANE (64 * HS_ROW_B)              // 66560
#define ZA_OFF (WT_OFF + 2 * WT_PLANE)        // 166400
#define ZB_OFF (ZA_OFF + GB * 64 * 4)         // 170496
#define STEP_SMEM_BYTES (ZB_OFF + 64 * 17 * 4)  // 175120

__global__ __launch_bounds__(256, 1) void lstm_layer_kernel(
    const float* __restrict__ A, const float* __restrict__ Wr,
    const int* __restrict__ lengths, __half* __restrict__ hbuf,
    float* __restrict__ H) {
    extern __shared__ char smc[];
    char* hsH = smc;
    __half* WtH = (__half*)(smc + WT_OFF);
    __half* WtL = (__half*)(smc + WT_OFF + WT_PLANE);
    float* za = (float*)(smc + ZA_OFF);   // [16 b][64 n]
    float* zb = (float*)(smc + ZB_OFF);   // [64 n][17] (padded)
    const int tid = threadIdx.x;
    const int bid = blockIdx.x;
    const int grp = bid >> 5;             // batch group 0..3
    const int gb0 = grp * GB;             // first global batch of group
    const int u0 = (bid & 31) * 16;       // first unit of this CTA
    const unsigned hsH_s = (unsigned)__cvta_generic_to_shared(hsH);
    const unsigned hsL_s = hsH_s + HS_PLANE;

    // per-layer flag base: all flags equal at kernel entry (each CTA bumps
    // exactly Tt times per layer; kernel boundary orders the last bumps)
    unsigned* myflag = &g_flag[bid * 32];
    const unsigned base = ld_acq(myflag);
    // this thread's cp.async items depend on exactly one writer per chunk:
    const int wsub = (tid & 15) >> 1;     // writer sub-index within chunk

    // prepack Wr slice -> hi/lo planes Wt[n][k], n = gate*16 + unit_local
    for (int i = tid; i < 64 * Uu; i += 256) {
        int n = i & 63, k = i >> 6;
        int gg = n >> 4, ul2 = n & 15;
        float w = Wr[(size_t)k * ZN + gg * Uu + u0 + ul2];
        __half whi = __float2half(w);
        WtH[n * WT_ROW_H + k] = whi;
        WtL[n * WT_ROW_H + k] = __float2half(w - __half2float(whi));
    }

    const int lane = tid & 31, warp = tid >> 5;
    const int fg = lane >> 2, tg = lane & 3;
    const int b = tid >> 4;               // group-local batch 0..15
    const int ul = tid & 15;              // unit-local 0..15
    const int ag = (tid & 15) >> 2;       // A-staging gate 0..3
    const int aj = tid & 3;               // A-staging chunk 0..3
    const int u = u0 + ul;
    const int len = lengths[gb0 + b];
    float creg = 0.f, hreg = 0.f;

    // prefetch A(0)
    const float* Abase = A + (size_t)(gb0 + b) * ZN + ag * Uu + u0 + aj * 4;
    float4 a4 = *(const float4*)Abase;

    for (int t = 0; t < Tt; t++) {
        float zi, zf, zg, zo;
        if (t == 0) {
            *(float4*)&za[b * 64 + ag * 16 + aj * 4] = a4;
            __syncthreads();
            zi = za[b * 64 + 0 * 16 + ul];
            zf = za[b * 64 + 1 * 16 + ul];
            zg = za[b * 64 + 2 * 16 + ul];
            zo = za[b * 64 + 3 * 16 + ul];
        } else {
            const __half* srcH =
                hbuf + (size_t)(t & 1) * (2 * Bb * Uu) + (size_t)gb0 * Uu;
            const __half* srcL = srcH + Bb * Uu;
            const unsigned tgt = base + (unsigned)t;

            // per-chunk: poll this thread's writer flag, then issue 2 cp.async
#define ISSUE_CHUNK(c)                                                        \
    {                                                                         \
        const unsigned* wf = &g_flag[((grp * GCTA) + (c)*8 + wsub) * 32];     \
        while ((int)(ld_acq(wf) - tgt) < 0) {                                 \
        }                                                                     \
        _Pragma("unroll") for (int j = 0; j < 2; j++) {                       \
            int item = tid + j * 256;                                         \
            int p = item >> 8;                                                \
            int row = (item >> 4) & 15;                                       \
            int c16 = (c)*16 + (item & 15);                                   \
            const __half* s = (p ? srcL : srcH) + row * Uu + c16 * 8;         \
            unsigned d = (p ? hsL_s : hsH_s) +                                \
                         (unsigned)(row * HS_ROW_B + c16 * 16);               \
            cp_async16(d, s);                                                 \
        }                                                                     \
        asm volatile("cp.async.commit_group;" ::: "memory");                  \
    }

            *(float4*)&za[b * 64 + ag * 16 + aj * 4] = a4;

            float hh0 = 0.f, hh1 = 0.f, hh2 = 0.f, hh3 = 0.f;
            float lh0 = 0.f, lh1 = 0.f, lh2 = 0.f, lh3 = 0.f;
            float hl0 = 0.f, hl1 = 0.f, hl2 = 0.f, hl3 = 0.f;

#define MMA_CHUNK(c)                                                          \
    {                                                                         \
        __syncthreads();                                                      \
        _Pragma("unroll") for (int kt = 0; kt < 8; kt++) {                    \
            int k0 = (c)*128 + kt * 16;                                       \
            const char* arH = hsH + fg * HS_ROW_B + (k0 + 2 * tg) * 2;        \
            uint32_t ah0 = *(const uint32_t*)(arH);                           \
            uint32_t ah1 = *(const uint32_t*)(arH + 8 * HS_ROW_B);            \
            uint32_t ah2 = *(const uint32_t*)(arH + 16);                      \
            uint32_t ah3 = *(const uint32_t*)(arH + 8 * HS_ROW_B + 16);       \
            const char* arL = arH + HS_PLANE;                                 \
            uint32_t al0 = *(const uint32_t*)(arL);                           \
            uint32_t al1 = *(const uint32_t*)(arL + 8 * HS_ROW_B);            \
            uint32_t al2 = *(const uint32_t*)(arL + 16);                      \
            uint32_t al3 = *(const uint32_t*)(arL + 8 * HS_ROW_B + 16);       \
            const __half* brH = WtH + (warp * 8 + fg) * WT_ROW_H + k0 + 2 * tg; \
            uint32_t bh0 = *(const uint32_t*)(brH);                           \
            uint32_t bh1 = *(const uint32_t*)(brH + 8);                       \
            const __half* brL = WtL + (warp * 8 + fg) * WT_ROW_H + k0 + 2 * tg; \
            uint32_t bl0 = *(const uint32_t*)(brL);                           \
            uint32_t bl1 = *(const uint32_t*)(brL + 8);                       \
            mma16816(hh0, hh1, hh2, hh3, ah0, ah1, ah2, ah3, bh0, bh1);       \
            mma16816(lh0, lh1, lh2, lh3, al0, al1, al2, al3, bh0, bh1);       \
            mma16816(hl0, hl1, hl2, hl3, ah0, ah1, ah2, ah3, bl0, bl1);       \
        }                                                                     \
    }

            ISSUE_CHUNK(0)
            ISSUE_CHUNK(1)
            asm volatile("cp.async.wait_group 1;" ::: "memory");
            MMA_CHUNK(0)
            ISSUE_CHUNK(2)
            asm volatile("cp.async.wait_group 1;" ::: "memory");
            MMA_CHUNK(1)
            ISSUE_CHUNK(3)
            asm volatile("cp.async.wait_group 1;" ::: "memory");
            MMA_CHUNK(2)
            asm volatile("cp.async.wait_group 0;" ::: "memory");
            MMA_CHUNK(3)
#undef ISSUE_CHUNK
#undef MMA_CHUNK

            float d0 = (hh0 + lh0) + hl0;
            float d1 = (hh1 + lh1) + hl1;
            float d2 = (hh2 + lh2) + hl2;
            float d3 = (hh3 + lh3) + hl3;
            zb[(warp * 8 + 2 * tg) * 17 + fg] = d0;
            zb[(warp * 8 + 2 * tg + 1) * 17 + fg] = d1;
            zb[(warp * 8 + 2 * tg) * 17 + fg + 8] = d2;
            zb[(warp * 8 + 2 * tg + 1) * 17 + fg + 8] = d3;
            __syncthreads();
            zi = zb[(0 * 16 + ul) * 17 + b] + za[b * 64 + 0 * 16 + ul];
            zf = zb[(1 * 16 + ul) * 17 + b] + za[b * 64 + 1 * 16 + ul];
            zg = zb[(2 * 16 + ul) * 17 + b] + za[b * 64 + 2 * 16 + ul];
            zo = zb[(3 * 16 + ul) * 17 + b] + za[b * 64 + 3 * 16 + ul];
        }

        float ig = fast_sig(zi);
        float fg2 = fast_sig(zf);
        float gv = fast_tanh(zg);
        float og = fast_sig(zo);
        float cn = fg2 * creg + ig * gv;
        float hn = og * fast_tanh(cn);

        bool msk = t < len;
        if (msk) {
            creg = cn;
            hreg = hn;
        }
        // split h for next step
        {
            __half hhi = __float2half(hreg);
            __half hlo = __float2half(hreg - __half2float(hhi));
            size_t bse = (size_t)((t + 1) & 1) * (2 * Bb * Uu) +
                         (size_t)(gb0 + b) * Uu + u;
            hbuf[bse] = hhi;
            hbuf[bse + Bb * Uu] = hlo;
        }
        H[((size_t)t * Bb + gb0 + b) * Uu + u] = msk ? hn : 0.f;

        // prefetch A(t+1) (latency hidden under flag publish + next polls)
        if (t + 1 < Tt)
            a4 = *(const float4*)(Abase + (size_t)(t + 1) * Bb * ZN);

        // publish progress: h(t) written -> flag = base + t + 1
        __threadfence();
        __syncthreads();
        if (tid == 0) st_rel(myflag, base + (unsigned)t + 1u);
    }
}

// ---------------- host: enqueue the whole pipeline (7 graph nodes) ---------
extern "C" void kernel_launch(void* const* d_in, const int* in_sizes, int n_in,
                              void* d_out, int out_size) {
    const int* tokens = (const int*)d_in[0];
    const int* lengths = (const int*)d_in[1];
    const float* emb = (const float*)d_in[2];
    const float* Wk[3] = {(const float*)d_in[3], (const float*)d_in[6],
                          (const float*)d_in[9]};
    const float* Wr[3] = {(const float*)d_in[4], (const float*)d_in[7],
                          (const float*)d_in[10]};
    const float* bv[3] = {(const float*)d_in[5], (const float*)d_in[8],
                          (const float*)d_in[11]};
    const float* Wd = (const float*)d_in[12];
    const float* bd = (const float*)d_in[13];
    float* out = (float*)d_out;

    float *A, *H;
    __half* hbuf;
    cudaGetSymbolAddress((void**)&A, g_A);
    cudaGetSymbolAddress((void**)&H, g_H);
    cudaGetSymbolAddress((void**)&hbuf, g_hbuf);

    cudaFuncSetAttribute(lstm_layer_kernel,
                         cudaFuncAttributeMaxDynamicSharedMemorySize,
                         STEP_SMEM_BYTES);

    dim3 blk(256);
    dim3 ggrid(ZN / 64, (Bb * Tt) / 128);
    // layer-0 input preactivation: A = emb[tokens] @ Wk0 + b0
    hgemm_kernel<1, 0><<<ggrid, blk>>>(nullptr, tokens, emb, Wk[0], bv[0], A,
                                       Ee, ZN);

    for (int l = 0; l < 3; l++) {
        if (l > 0) {
            // A = H_{l-1} @ Wk_l + b_l   (H fp32 row-major [m][K])
            hgemm_kernel<2, 0><<<ggrid, blk>>>(H, nullptr, nullptr, Wk[l],
                                               bv[l], A, Uu, ZN);
        }
        lstm_layer_kernel<<<NCTA, 256, STEP_SMEM_BYTES>>>(A, Wr[l], lengths,
                                                          hbuf, H);
    }
    // logits = H_2 @ Wd + bd, permuted to [b][t][v]
    hgemm_kernel<2, 1><<<dim3(Vv / 64, (Bb * Tt) / 128), blk>>>(
        H, nullptr, nullptr, Wd, bd, out, Uu, Vv);
}